// round 15
// baseline (speedup 1.0000x reference)
#include <cuda_runtime.h>
#include <cuda_fp16.h>
#include <cstdint>

// ============================================================================
// out = alpha*x + U * diag(g(lam)) * U^T * x       (Lambda diagonal)
// g(l) = sum_i 4*c_i/(a_i-b_i)^2 * relu((a_i-l)(l-b_i))
//
// Engine: mma.sync m16n8k16 fp16 (fp32 accum).  R14: asymmetric precision —
// U carried as fp16 hi/lo (~22-bit), X and W as single fp16 (11-bit).
// 2 MMAs per product instead of 3:
//   GEMM1: D = Xt * Uth^T + Xt * Utl^T     (A single, B hi/lo)
//   GEMM2: D = Uh * Wt^T + Ul * Wt^T       (A hi/lo via trans-LDSM, B single)
// Structure otherwise = R12 (55.6us): split-K=4, 128x64 CTA, 8 warps 32x32,
// separate light merge kernels.
// ============================================================================

#define NDIM 2048
#define FDIM 256
#define KDIM 2048
#define SPLITK 4
#define KSPLIT (KDIM / SPLITK)   // 512
#define BM   128
#define BN   64
#define KT   64
#define NKT  (KSPLIT / KT)       // 8

// GEMM1 stage: A 16K | BH 8K | BL 8K = 32K
#define G1_OFF_BH 16384
#define G1_OFF_BL 24576
#define G1_STAGE  32768
#define G1_SMEM   (1024 + 2 * G1_STAGE)    // 66560
// GEMM2 stage: AH 16K | AL 16K | B 8K = 40K
#define G2_OFF_AL 16384
#define G2_OFF_B  32768
#define G2_STAGE  40960
#define G2_SMEM   (1024 + 2 * G2_STAGE)    // 82944

// ------------------------- device scratch (no cudaMalloc) -------------------
__device__ __align__(16) __half g_Uthi[NDIM * NDIM];
__device__ __align__(16) __half g_Utlo[NDIM * NDIM];
__device__ __align__(16) __half g_Xt  [FDIM * NDIM];
__device__ __align__(16) __half g_Wt  [FDIM * NDIM];
__device__ __align__(16) float g_p[SPLITK][FDIM * NDIM];   // GEMM1 partials
__device__ __align__(16) float g_q[SPLITK][NDIM * FDIM];   // GEMM2 partials
__device__ float g_g[NDIM];

// ------------------------------- helpers ------------------------------------
__device__ __forceinline__ unsigned s2u(const void* p) {
    unsigned a;
    asm("{ .reg .u64 t; cvta.to.shared.u64 t, %1; cvt.u32.u64 %0, t; }" : "=r"(a) : "l"(p));
    return a;
}
__device__ __forceinline__ unsigned swz(unsigned o) { return o ^ ((o >> 3) & 0x70); }

__device__ __forceinline__ void cpa16(unsigned s, const void* g) {
    asm volatile("cp.async.cg.shared.global [%0], [%1], 16;" :: "r"(s), "l"(g));
}
__device__ __forceinline__ void ldm_x4(unsigned* r, unsigned addr) {
    asm volatile("ldmatrix.sync.aligned.m8n8.x4.shared.b16 {%0,%1,%2,%3}, [%4];"
                 : "=r"(r[0]), "=r"(r[1]), "=r"(r[2]), "=r"(r[3]) : "r"(addr));
}
__device__ __forceinline__ void ldm_x4_t(unsigned* r, unsigned addr) {
    asm volatile("ldmatrix.sync.aligned.m8n8.x4.trans.shared.b16 {%0,%1,%2,%3}, [%4];"
                 : "=r"(r[0]), "=r"(r[1]), "=r"(r[2]), "=r"(r[3]) : "r"(addr));
}
__device__ __forceinline__ void mma16816(float* d, const unsigned* a, const unsigned* b) {
    asm volatile("mma.sync.aligned.m16n8k16.row.col.f32.f16.f16.f32 "
                 "{%0,%1,%2,%3}, {%4,%5,%6,%7}, {%8,%9}, {%0,%1,%2,%3};"
                 : "+f"(d[0]), "+f"(d[1]), "+f"(d[2]), "+f"(d[3])
                 : "r"(a[0]), "r"(a[1]), "r"(a[2]), "r"(a[3]), "r"(b[0]), "r"(b[1]));
}

// ------------------------------ prep kernels --------------------------------
__global__ void prep_g_k(const float* __restrict__ lam, const float* __restrict__ a,
                         const float* __restrict__ b, const float* __restrict__ c, int nf) {
    int j = blockIdx.x * blockDim.x + threadIdx.x;
    if (j >= NDIM) return;
    float lv = lam[(size_t)j * NDIM + j];
    float g = 0.f;
    for (int i = 0; i < nf; ++i) {
        float at = a[i], bt = b[i];
        float d = (at - lv) * (lv - bt);
        d = d > 0.f ? d : 0.f;
        float ab = at - bt;
        g += (4.f * c[i] / (ab * ab)) * d;
    }
    g_g[j] = g;
}

// U -> Ut hi/lo (fp16 pair, ~22-bit effective)
__global__ void prep_U_k(const float* __restrict__ U) {
    __shared__ float t[32][33];
    const int bx = blockIdx.x * 32, by = blockIdx.y * 32;
    const int tx = threadIdx.x, ty = threadIdx.y;
#pragma unroll
    for (int i = 0; i < 4; ++i) {
        int r = ty + i * 8;
        t[r][tx] = U[(size_t)(by + r) * NDIM + bx + tx];
    }
    __syncthreads();
#pragma unroll
    for (int i = 0; i < 4; ++i) {
        int r = ty + i * 8;
        float v = t[tx][r];                            // U[by+tx, bx+r]
        __half h = __float2half_rn(v);
        size_t o = (size_t)(bx + r) * NDIM + by + tx;  // Ut[bx+r, by+tx]
        g_Uthi[o] = h;
        g_Utlo[o] = __float2half_rn(v - __half2float(h));
    }
}

// X -> Xt (single fp16)
__global__ void prep_X_k(const float* __restrict__ X) {
    __shared__ float t[32][33];
    const int bx = blockIdx.x * 32, by = blockIdx.y * 32;   // bx over F, by over N
    const int tx = threadIdx.x, ty = threadIdx.y;
#pragma unroll
    for (int i = 0; i < 4; ++i) {
        int r = ty + i * 8;
        t[r][tx] = X[(size_t)(by + r) * FDIM + bx + tx];
    }
    __syncthreads();
#pragma unroll
    for (int i = 0; i < 4; ++i) {
        int r = ty + i * 8;
        float v = t[tx][r];                            // X[by+tx, bx+r]
        g_Xt[(size_t)(bx + r) * NDIM + by + tx] = __float2half_rn(v);
    }
}

// ------------------------------ merge kernels -------------------------------
// merge1: Wt = g[col] * sum_z p[z]  -> single fp16   [FDIM x NDIM]
__global__ void merge1_k() {
    int i4 = (blockIdx.x * 256 + threadIdx.x) * 4;
    int col = i4 & (NDIM - 1);
    float4 p0 = *(const float4*)(g_p[0] + i4);
    float4 p1 = *(const float4*)(g_p[1] + i4);
    float4 p2 = *(const float4*)(g_p[2] + i4);
    float4 p3 = *(const float4*)(g_p[3] + i4);
    float4 gg = *(const float4*)(g_g + col);
    __half hv[4];
    hv[0] = __float2half_rn(((p0.x + p1.x) + (p2.x + p3.x)) * gg.x);
    hv[1] = __float2half_rn(((p0.y + p1.y) + (p2.y + p3.y)) * gg.y);
    hv[2] = __float2half_rn(((p0.z + p1.z) + (p2.z + p3.z)) * gg.z);
    hv[3] = __float2half_rn(((p0.w + p1.w) + (p2.w + p3.w)) * gg.w);
    *(uint2*)(g_Wt + i4) = *(uint2*)hv;
}

// merge2: out = alpha*X + sum_z q[z]                 [NDIM x FDIM]
__global__ void merge2_k(const float* __restrict__ X,
                         const float* __restrict__ alpha, float* __restrict__ out) {
    int i4 = (blockIdx.x * 256 + threadIdx.x) * 4;
    const float av = alpha[0];
    float4 q0 = *(const float4*)(g_q[0] + i4);
    float4 q1 = *(const float4*)(g_q[1] + i4);
    float4 q2 = *(const float4*)(g_q[2] + i4);
    float4 q3 = *(const float4*)(g_q[3] + i4);
    float4 xv = *(const float4*)(X + i4);
    float4 o;
    o.x = av * xv.x + (q0.x + q1.x) + (q2.x + q3.x);
    o.y = av * xv.y + (q0.y + q1.y) + (q2.y + q3.y);
    o.z = av * xv.z + (q0.z + q1.z) + (q2.z + q3.z);
    o.w = av * xv.w + (q0.w + q1.w) + (q2.w + q3.w);
    *(float4*)(out + i4) = o;
}

// ----------------------------- GEMM1 kernel ---------------------------------
// p[z] = Xt[m0..,k] * Ut[n0..,k]^T ;  A single fp16, B = Ut hi/lo.
// 8 warps as 4(m) x 2(n), warp tile 32x32.  2 MMAs per (mf,nf,ks).
__global__ __launch_bounds__(256, 2)
void gemm1_k()
{
    extern __shared__ char smem_raw[];
    const unsigned sb = (s2u(smem_raw) + 1023u) & ~1023u;

    const int tid = threadIdx.x;
    const int wid = tid >> 5, lane = tid & 31;
    const int warp_m = wid >> 1, warp_n = wid & 1;
    const int m0 = blockIdx.x * BM, n0 = blockIdx.y * BN;
    const int kofs = blockIdx.z * KSPLIT;
    float* pout = g_p[blockIdx.z];

    const __half* baseA  = g_Xt   + (size_t)m0 * KDIM + kofs;
    const __half* baseBh = g_Uthi + (size_t)n0 * KDIM + kofs;
    const __half* baseBl = g_Utlo + (size_t)n0 * KDIM + kofs;

    // 8 chunks/thread: [0,1024)=A, [1024,1536)=BH, [1536,2048)=BL
    const __half* srcp[8];
    unsigned soff[8], goff[8];
#pragma unroll
    for (int i = 0; i < 8; ++i) {
        int l = i * 256 + tid;
        unsigned rofs; int lr;
        if (l < 1024)      { rofs = 0u;        lr = l;        srcp[i] = baseA;  }
        else if (l < 1536) { rofs = G1_OFF_BH; lr = l - 1024; srcp[i] = baseBh; }
        else               { rofs = G1_OFF_BL; lr = l - 1536; srcp[i] = baseBl; }
        int row = lr >> 3, c = lr & 7;
        soff[i] = rofs + swz(row * 128 + c * 16);
        goff[i] = row * KDIM + c * 8;
    }

    auto load_tile = [&](int t, int stage) {
        const unsigned st = sb + stage * G1_STAGE;
        const unsigned kb = t * KT;
#pragma unroll
        for (int i = 0; i < 8; ++i)
            cpa16(st + soff[i], srcp[i] + goff[i] + kb);
        asm volatile("cp.async.commit_group;" ::: "memory");
    };

    unsigned abase[2], bbase[2];
#pragma unroll
    for (int mf = 0; mf < 2; ++mf) {
        int rowA = warp_m * 32 + mf * 16 + ((lane >> 3) & 1) * 8 + (lane & 7);
        abase[mf] = rowA * 128 + (lane >> 4) * 16;
    }
#pragma unroll
    for (int nf2 = 0; nf2 < 2; ++nf2) {
        int rowB = warp_n * 32 + nf2 * 16 + ((lane >> 4) & 1) * 8 + (lane & 7);
        bbase[nf2] = rowB * 128 + ((lane >> 3) & 1) * 16;
    }

    float acc[2][4][4] = {};

    load_tile(0, 0);
    for (int t = 0; t < NKT; ++t) {
        if (t + 1 < NKT) {
            load_tile(t + 1, (t + 1) & 1);
            asm volatile("cp.async.wait_group 1;" ::: "memory");
        } else {
            asm volatile("cp.async.wait_group 0;" ::: "memory");
        }
        __syncthreads();

        const unsigned stA = sb + (t & 1) * G1_STAGE;
        const unsigned stB = stA + G1_OFF_BH;
#pragma unroll
        for (int ks = 0; ks < 4; ++ks) {
            unsigned ah[2][4], bh[2][4], bl[2][4];
#pragma unroll
            for (int mf = 0; mf < 2; ++mf)
                ldm_x4(ah[mf], stA + swz(abase[mf] + ks * 32));
#pragma unroll
            for (int nf2 = 0; nf2 < 2; ++nf2) {
                ldm_x4(bh[nf2], stB + swz(bbase[nf2] + ks * 32));
                ldm_x4(bl[nf2], stB + (G1_OFF_BL - G1_OFF_BH) + swz(bbase[nf2] + ks * 32));
            }
#pragma unroll
            for (int mf = 0; mf < 2; ++mf) {
#pragma unroll
                for (int nf = 0; nf < 4; ++nf)
                    mma16816(acc[mf][nf], ah[mf], &bh[nf >> 1][(nf & 1) * 2]);
#pragma unroll
                for (int nf = 0; nf < 4; ++nf)
                    mma16816(acc[mf][nf], ah[mf], &bl[nf >> 1][(nf & 1) * 2]);
            }
        }
        __syncthreads();
    }

    const int rbase = m0 + warp_m * 32 + (lane >> 2);
    const int cbase0 = n0 + warp_n * 32 + (lane & 3) * 2;
#pragma unroll
    for (int mf = 0; mf < 2; ++mf)
#pragma unroll
        for (int nf = 0; nf < 4; ++nf) {
            const int cb = cbase0 + nf * 8;
#pragma unroll
            for (int h = 0; h < 2; ++h) {
                const int row = rbase + mf * 16 + h * 8;
                float2 v;
                v.x = acc[mf][nf][h * 2 + 0];
                v.y = acc[mf][nf][h * 2 + 1];
                *(float2*)(pout + (size_t)row * NDIM + cb) = v;
            }
        }
}

// ----------------------------- GEMM2 kernel ---------------------------------
// q[z] = U[m0..,j] * Wt[n0..,j]^T ; A = Ut hi/lo via trans-LDSM, B = Wt single.
// A stage: 2 subtiles (m blocks of 64), each 64 krows x 128B.
__global__ __launch_bounds__(256, 2)
void gemm2_k()
{
    extern __shared__ char smem_raw[];
    const unsigned sb = (s2u(smem_raw) + 1023u) & ~1023u;

    const int tid = threadIdx.x;
    const int wid = tid >> 5, lane = tid & 31;
    const int warp_m = wid >> 1, warp_n = wid & 1;
    const int m0 = blockIdx.x * BM, n0 = blockIdx.y * BN;
    const int kofs = blockIdx.z * KSPLIT;
    float* pout = g_q[blockIdx.z];

    const __half* baseAh = g_Uthi + (size_t)kofs * NDIM + m0;
    const __half* baseAl = g_Utlo + (size_t)kofs * NDIM + m0;
    const __half* baseB  = g_Wt   + (size_t)n0 * KDIM + kofs;

    // 10 chunks/thread: [0,1024)=AH, [1024,2048)=AL, [2048,2560)=B
    const __half* srcp[10];
    unsigned soff[10], goff[10], kmul[10];
#pragma unroll
    for (int i = 0; i < 10; ++i) {
        int l = i * 256 + tid;
        if (l < 2048) {
            int islo = l >= 1024;
            int lr = l & 1023;
            int sub = lr >> 9;
            int lrr = lr & 511;
            int row = lrr >> 3, c = lrr & 7;        // row = k row, c = m chunk
            soff[i] = (islo ? G2_OFF_AL : 0u) + sub * 8192 + swz(row * 128 + c * 16);
            goff[i] = row * NDIM + sub * 64 + c * 8;
            srcp[i] = islo ? baseAl : baseAh;
            kmul[i] = KT * NDIM;
        } else {
            int lr = l - 2048;
            int row = lr >> 3, c = lr & 7;
            soff[i] = G2_OFF_B + swz(row * 128 + c * 16);
            goff[i] = row * KDIM + c * 8;
            srcp[i] = baseB;
            kmul[i] = KT;
        }
    }

    auto load_tile = [&](int t, int stage) {
        const unsigned st = sb + stage * G2_STAGE;
#pragma unroll
        for (int i = 0; i < 10; ++i)
            cpa16(st + soff[i], srcp[i] + goff[i] + (size_t)t * kmul[i]);
        asm volatile("cp.async.commit_group;" ::: "memory");
    };

    const unsigned asub = (warp_m >> 1) * 8192;
    unsigned abase_t[2];
#pragma unroll
    for (int mf = 0; mf < 2; ++mf) {
        int rowk = ((lane >> 4) & 1) * 8 + (lane & 7);
        int colb = (warp_m & 1) * 64 + mf * 32 + ((lane >> 3) & 1) * 16;
        abase_t[mf] = rowk * 128 + colb;
    }
    unsigned bbase[2];
#pragma unroll
    for (int nf2 = 0; nf2 < 2; ++nf2) {
        int rowB = warp_n * 32 + nf2 * 16 + ((lane >> 4) & 1) * 8 + (lane & 7);
        bbase[nf2] = rowB * 128 + ((lane >> 3) & 1) * 16;
    }

    float acc[2][4][4] = {};

    load_tile(0, 0);
    for (int t = 0; t < NKT; ++t) {
        if (t + 1 < NKT) {
            load_tile(t + 1, (t + 1) & 1);
            asm volatile("cp.async.wait_group 1;" ::: "memory");
        } else {
            asm volatile("cp.async.wait_group 0;" ::: "memory");
        }
        __syncthreads();

        const unsigned stA = sb + (t & 1) * G2_STAGE;
        const unsigned stB = stA + G2_OFF_B;
#pragma unroll
        for (int ks = 0; ks < 4; ++ks) {
            unsigned ah[2][4], al[2][4], bf[2][4];
#pragma unroll
            for (int mf = 0; mf < 2; ++mf) {
                ldm_x4_t(ah[mf], stA + asub + swz(abase_t[mf] + ks * 2048));
                ldm_x4_t(al[mf], stA + G2_OFF_AL + asub + swz(abase_t[mf] + ks * 2048));
            }
#pragma unroll
            for (int nf2 = 0; nf2 < 2; ++nf2)
                ldm_x4(bf[nf2], stB + swz(bbase[nf2] + ks * 32));
#pragma unroll
            for (int mf = 0; mf < 2; ++mf) {
#pragma unroll
                for (int nf = 0; nf < 4; ++nf)
                    mma16816(acc[mf][nf], ah[mf], &bf[nf >> 1][(nf & 1) * 2]);
#pragma unroll
                for (int nf = 0; nf < 4; ++nf)
                    mma16816(acc[mf][nf], al[mf], &bf[nf >> 1][(nf & 1) * 2]);
            }
        }
        __syncthreads();
    }

    const int rbase = m0 + warp_m * 32 + (lane >> 2);
    const int cbase0 = n0 + warp_n * 32 + (lane & 3) * 2;
#pragma unroll
    for (int mf = 0; mf < 2; ++mf)
#pragma unroll
        for (int nf = 0; nf < 4; ++nf) {
            const int cb = cbase0 + nf * 8;
#pragma unroll
            for (int h = 0; h < 2; ++h) {
                const int row = rbase + mf * 16 + h * 8;
                float2 v;
                v.x = acc[mf][nf][h * 2 + 0];
                v.y = acc[mf][nf][h * 2 + 1];
                *(float2*)(pout + (size_t)row * FDIM + cb) = v;
            }
        }
}

// ---------------------------------------------------------------------------
extern "C" void kernel_launch(void* const* d_in, const int* in_sizes, int n_in,
                              void* d_out, int out_size)
{
    const float* X     = (const float*)d_in[0];  // [N,F]
    const float* Lam   = (const float*)d_in[1];  // [N,N] diagonal
    const float* U     = (const float*)d_in[2];  // [N,N]
    const float* a     = (const float*)d_in[3];
    const float* b     = (const float*)d_in[4];
    const float* c     = (const float*)d_in[5];
    const float* alpha = (const float*)d_in[6];
    // d_in[7] = edge_index (unused by the reference math)
    const int nf = in_sizes[3];

    static bool attr_set = false;
    if (!attr_set) {
        cudaFuncSetAttribute(gemm1_k, cudaFuncAttributeMaxDynamicSharedMemorySize, G1_SMEM);
        cudaFuncSetAttribute(gemm2_k, cudaFuncAttributeMaxDynamicSharedMemorySize, G2_SMEM);
        attr_set = true;
    }

    prep_g_k<<<NDIM / 256, 256>>>(Lam, a, b, c, nf);
    dim3 bt(32, 8);
    prep_X_k<<<dim3(FDIM / 32, NDIM / 32), bt>>>(X);
    prep_U_k<<<dim3(NDIM / 32, NDIM / 32), bt>>>(U);

    // GEMM1: grid 2 x 32 x 4 = 256 CTAs
    gemm1_k<<<dim3(FDIM / BM, NDIM / BN, SPLITK), 256, G1_SMEM>>>();
    merge1_k<<<(FDIM * NDIM / 4) / 256, 256>>>();
    // GEMM2: grid 16 x 4 x 4 = 256 CTAs
    gemm2_k<<<dim3(NDIM / BM, FDIM / BN, SPLITK), 256, G2_SMEM>>>();
    merge2_k<<<(NDIM * FDIM / 4) / 256, 256>>>(X, alpha, (float*)d_out);
}

// round 16
// speedup vs baseline: 1.3782x; 1.3782x over previous
#include <cuda_runtime.h>
#include <cuda_fp16.h>
#include <cstdint>

// ============================================================================
// out = alpha*x + U * diag(g(lam)) * U^T * x       (Lambda diagonal)
// g(l) = sum_i 4*c_i/(a_i-b_i)^2 * relu((a_i-l)(l-b_i))
//
// Engine: mma.sync m16n8k16 fp16 (fp32 accum).  R16: single fp16 for ALL
// operands -> 1 MMA per product (error budget: ~2.5-3.5e-4 vs 1e-3 gate,
// measured 1.76e-4 with X/W quantized; U adds two similar sources).
//   GEMM1: D = Xt * Ut^T          GEMM2: D = U * Wt^T  (A via trans-LDSM)
// Structure = R15: split-K=4, 128x64 CTA, 8 warps 32x32, light merges.
// ============================================================================

#define NDIM 2048
#define FDIM 256
#define KDIM 2048
#define SPLITK 4
#define KSPLIT (KDIM / SPLITK)   // 512
#define BM   128
#define BN   64
#define KT   64
#define NKT  (KSPLIT / KT)       // 8

// stage: A 16K | B 8K = 24K  (same layout both GEMMs)
#define OFF_B  16384
#define STAGE  24576
#define SMEM_G (1024 + 2 * STAGE)   // 50176

// ------------------------- device scratch (no cudaMalloc) -------------------
__device__ __align__(16) __half g_Ut[NDIM * NDIM];
__device__ __align__(16) __half g_Xt[FDIM * NDIM];
__device__ __align__(16) __half g_Wt[FDIM * NDIM];
__device__ __align__(16) float g_p[SPLITK][FDIM * NDIM];   // GEMM1 partials
__device__ __align__(16) float g_q[SPLITK][NDIM * FDIM];   // GEMM2 partials
__device__ float g_g[NDIM];

// ------------------------------- helpers ------------------------------------
__device__ __forceinline__ unsigned s2u(const void* p) {
    unsigned a;
    asm("{ .reg .u64 t; cvta.to.shared.u64 t, %1; cvt.u32.u64 %0, t; }" : "=r"(a) : "l"(p));
    return a;
}
__device__ __forceinline__ unsigned swz(unsigned o) { return o ^ ((o >> 3) & 0x70); }

__device__ __forceinline__ void cpa16(unsigned s, const void* g) {
    asm volatile("cp.async.cg.shared.global [%0], [%1], 16;" :: "r"(s), "l"(g));
}
__device__ __forceinline__ void ldm_x4(unsigned* r, unsigned addr) {
    asm volatile("ldmatrix.sync.aligned.m8n8.x4.shared.b16 {%0,%1,%2,%3}, [%4];"
                 : "=r"(r[0]), "=r"(r[1]), "=r"(r[2]), "=r"(r[3]) : "r"(addr));
}
__device__ __forceinline__ void ldm_x4_t(unsigned* r, unsigned addr) {
    asm volatile("ldmatrix.sync.aligned.m8n8.x4.trans.shared.b16 {%0,%1,%2,%3}, [%4];"
                 : "=r"(r[0]), "=r"(r[1]), "=r"(r[2]), "=r"(r[3]) : "r"(addr));
}
__device__ __forceinline__ void mma16816(float* d, const unsigned* a, const unsigned* b) {
    asm volatile("mma.sync.aligned.m16n8k16.row.col.f32.f16.f16.f32 "
                 "{%0,%1,%2,%3}, {%4,%5,%6,%7}, {%8,%9}, {%0,%1,%2,%3};"
                 : "+f"(d[0]), "+f"(d[1]), "+f"(d[2]), "+f"(d[3])
                 : "r"(a[0]), "r"(a[1]), "r"(a[2]), "r"(a[3]), "r"(b[0]), "r"(b[1]));
}

// ------------------------------ prep kernels --------------------------------
__global__ void prep_g_k(const float* __restrict__ lam, const float* __restrict__ a,
                         const float* __restrict__ b, const float* __restrict__ c, int nf) {
    int j = blockIdx.x * blockDim.x + threadIdx.x;
    if (j >= NDIM) return;
    float lv = lam[(size_t)j * NDIM + j];
    float g = 0.f;
    for (int i = 0; i < nf; ++i) {
        float at = a[i], bt = b[i];
        float d = (at - lv) * (lv - bt);
        d = d > 0.f ? d : 0.f;
        float ab = at - bt;
        g += (4.f * c[i] / (ab * ab)) * d;
    }
    g_g[j] = g;
}

__global__ void prep_U_k(const float* __restrict__ U) {
    __shared__ float t[32][33];
    const int bx = blockIdx.x * 32, by = blockIdx.y * 32;
    const int tx = threadIdx.x, ty = threadIdx.y;
#pragma unroll
    for (int i = 0; i < 4; ++i) {
        int r = ty + i * 8;
        t[r][tx] = U[(size_t)(by + r) * NDIM + bx + tx];
    }
    __syncthreads();
#pragma unroll
    for (int i = 0; i < 4; ++i) {
        int r = ty + i * 8;
        float v = t[tx][r];                            // U[by+tx, bx+r]
        g_Ut[(size_t)(bx + r) * NDIM + by + tx] = __float2half_rn(v);
    }
}

__global__ void prep_X_k(const float* __restrict__ X) {
    __shared__ float t[32][33];
    const int bx = blockIdx.x * 32, by = blockIdx.y * 32;   // bx over F, by over N
    const int tx = threadIdx.x, ty = threadIdx.y;
#pragma unroll
    for (int i = 0; i < 4; ++i) {
        int r = ty + i * 8;
        t[r][tx] = X[(size_t)(by + r) * FDIM + bx + tx];
    }
    __syncthreads();
#pragma unroll
    for (int i = 0; i < 4; ++i) {
        int r = ty + i * 8;
        float v = t[tx][r];                            // X[by+tx, bx+r]
        g_Xt[(size_t)(bx + r) * NDIM + by + tx] = __float2half_rn(v);
    }
}

// ------------------------------ merge kernels -------------------------------
// merge1: Wt = g[col] * sum_z p[z]  -> single fp16   [FDIM x NDIM]
__global__ void merge1_k() {
    int i4 = (blockIdx.x * 256 + threadIdx.x) * 4;
    int col = i4 & (NDIM - 1);
    float4 p0 = *(const float4*)(g_p[0] + i4);
    float4 p1 = *(const float4*)(g_p[1] + i4);
    float4 p2 = *(const float4*)(g_p[2] + i4);
    float4 p3 = *(const float4*)(g_p[3] + i4);
    float4 gg = *(const float4*)(g_g + col);
    __half hv[4];
    hv[0] = __float2half_rn(((p0.x + p1.x) + (p2.x + p3.x)) * gg.x);
    hv[1] = __float2half_rn(((p0.y + p1.y) + (p2.y + p3.y)) * gg.y);
    hv[2] = __float2half_rn(((p0.z + p1.z) + (p2.z + p3.z)) * gg.z);
    hv[3] = __float2half_rn(((p0.w + p1.w) + (p2.w + p3.w)) * gg.w);
    *(uint2*)(g_Wt + i4) = *(uint2*)hv;
}

// merge2: out = alpha*X + sum_z q[z]                 [NDIM x FDIM]
__global__ void merge2_k(const float* __restrict__ X,
                         const float* __restrict__ alpha, float* __restrict__ out) {
    int i4 = (blockIdx.x * 256 + threadIdx.x) * 4;
    const float av = alpha[0];
    float4 q0 = *(const float4*)(g_q[0] + i4);
    float4 q1 = *(const float4*)(g_q[1] + i4);
    float4 q2 = *(const float4*)(g_q[2] + i4);
    float4 q3 = *(const float4*)(g_q[3] + i4);
    float4 xv = *(const float4*)(X + i4);
    float4 o;
    o.x = av * xv.x + (q0.x + q1.x) + (q2.x + q3.x);
    o.y = av * xv.y + (q0.y + q1.y) + (q2.y + q3.y);
    o.z = av * xv.z + (q0.z + q1.z) + (q2.z + q3.z);
    o.w = av * xv.w + (q0.w + q1.w) + (q2.w + q3.w);
    *(float4*)(out + i4) = o;
}

// ----------------------------- GEMM1 kernel ---------------------------------
// p[z] = Xt[m0..,k] * Ut[n0..,k]^T ; both single fp16, 1 MMA per product.
__global__ __launch_bounds__(256, 2)
void gemm1_k()
{
    extern __shared__ char smem_raw[];
    const unsigned sb = (s2u(smem_raw) + 1023u) & ~1023u;

    const int tid = threadIdx.x;
    const int wid = tid >> 5, lane = tid & 31;
    const int warp_m = wid >> 1, warp_n = wid & 1;
    const int m0 = blockIdx.x * BM, n0 = blockIdx.y * BN;
    const int kofs = blockIdx.z * KSPLIT;
    float* pout = g_p[blockIdx.z];

    const __half* baseA = g_Xt + (size_t)m0 * KDIM + kofs;
    const __half* baseB = g_Ut + (size_t)n0 * KDIM + kofs;

    // 6 chunks/thread: [0,1024)=A, [1024,1536)=B
    const __half* srcp[6];
    unsigned soff[6], goff[6];
#pragma unroll
    for (int i = 0; i < 6; ++i) {
        int l = i * 256 + tid;
        unsigned rofs; int lr;
        if (l < 1024) { rofs = 0u;    lr = l;        srcp[i] = baseA; }
        else          { rofs = OFF_B; lr = l - 1024; srcp[i] = baseB; }
        int row = lr >> 3, c = lr & 7;
        soff[i] = rofs + swz(row * 128 + c * 16);
        goff[i] = row * KDIM + c * 8;
    }

    auto load_tile = [&](int t, int stage) {
        const unsigned st = sb + stage * STAGE;
        const unsigned kb = t * KT;
#pragma unroll
        for (int i = 0; i < 6; ++i)
            cpa16(st + soff[i], srcp[i] + goff[i] + kb);
        asm volatile("cp.async.commit_group;" ::: "memory");
    };

    unsigned abase[2], bbase[2];
#pragma unroll
    for (int mf = 0; mf < 2; ++mf) {
        int rowA = warp_m * 32 + mf * 16 + ((lane >> 3) & 1) * 8 + (lane & 7);
        abase[mf] = rowA * 128 + (lane >> 4) * 16;
    }
#pragma unroll
    for (int nf2 = 0; nf2 < 2; ++nf2) {
        int rowB = warp_n * 32 + nf2 * 16 + ((lane >> 4) & 1) * 8 + (lane & 7);
        bbase[nf2] = rowB * 128 + ((lane >> 3) & 1) * 16;
    }

    float acc[2][4][4] = {};

    load_tile(0, 0);
    for (int t = 0; t < NKT; ++t) {
        if (t + 1 < NKT) {
            load_tile(t + 1, (t + 1) & 1);
            asm volatile("cp.async.wait_group 1;" ::: "memory");
        } else {
            asm volatile("cp.async.wait_group 0;" ::: "memory");
        }
        __syncthreads();

        const unsigned stA = sb + (t & 1) * STAGE;
        const unsigned stB = stA + OFF_B;
#pragma unroll
        for (int ks = 0; ks < 4; ++ks) {
            unsigned ah[2][4], bf[2][4];
#pragma unroll
            for (int mf = 0; mf < 2; ++mf)
                ldm_x4(ah[mf], stA + swz(abase[mf] + ks * 32));
#pragma unroll
            for (int nf2 = 0; nf2 < 2; ++nf2)
                ldm_x4(bf[nf2], stB + swz(bbase[nf2] + ks * 32));
#pragma unroll
            for (int mf = 0; mf < 2; ++mf)
#pragma unroll
                for (int nf = 0; nf < 4; ++nf)
                    mma16816(acc[mf][nf], ah[mf], &bf[nf >> 1][(nf & 1) * 2]);
        }
        __syncthreads();
    }

    const int rbase = m0 + warp_m * 32 + (lane >> 2);
    const int cbase0 = n0 + warp_n * 32 + (lane & 3) * 2;
#pragma unroll
    for (int mf = 0; mf < 2; ++mf)
#pragma unroll
        for (int nf = 0; nf < 4; ++nf) {
            const int cb = cbase0 + nf * 8;
#pragma unroll
            for (int h = 0; h < 2; ++h) {
                const int row = rbase + mf * 16 + h * 8;
                float2 v;
                v.x = acc[mf][nf][h * 2 + 0];
                v.y = acc[mf][nf][h * 2 + 1];
                *(float2*)(pout + (size_t)row * NDIM + cb) = v;
            }
        }
}

// ----------------------------- GEMM2 kernel ---------------------------------
// q[z] = U[m0..,j] * Wt[n0..,j]^T ; A from Ut via trans-LDSM, B = Wt.
// A stage: 2 subtiles (m blocks of 64), each 64 krows x 128B.
__global__ __launch_bounds__(256, 2)
void gemm2_k()
{
    extern __shared__ char smem_raw[];
    const unsigned sb = (s2u(smem_raw) + 1023u) & ~1023u;

    const int tid = threadIdx.x;
    const int wid = tid >> 5, lane = tid & 31;
    const int warp_m = wid >> 1, warp_n = wid & 1;
    const int m0 = blockIdx.x * BM, n0 = blockIdx.y * BN;
    const int kofs = blockIdx.z * KSPLIT;
    float* pout = g_q[blockIdx.z];

    const __half* baseA = g_Ut + (size_t)kofs * NDIM + m0;
    const __half* baseB = g_Wt + (size_t)n0 * KDIM + kofs;

    // 6 chunks/thread: [0,1024)=A (2 subtiles), [1024,1536)=B
    const __half* srcp[6];
    unsigned soff[6], goff[6], kmul[6];
#pragma unroll
    for (int i = 0; i < 6; ++i) {
        int l = i * 256 + tid;
        if (l < 1024) {
            int sub = l >> 9;
            int lr = l & 511;
            int row = lr >> 3, c = lr & 7;          // row = k row, c = m chunk
            soff[i] = sub * 8192 + swz(row * 128 + c * 16);
            goff[i] = row * NDIM + sub * 64 + c * 8;
            srcp[i] = baseA;
            kmul[i] = KT * NDIM;
        } else {
            int lr = l - 1024;
            int row = lr >> 3, c = lr & 7;
            soff[i] = OFF_B + swz(row * 128 + c * 16);
            goff[i] = row * KDIM + c * 8;
            srcp[i] = baseB;
            kmul[i] = KT;
        }
    }

    auto load_tile = [&](int t, int stage) {
        const unsigned st = sb + stage * STAGE;
#pragma unroll
        for (int i = 0; i < 6; ++i)
            cpa16(st + soff[i], srcp[i] + goff[i] + (size_t)t * kmul[i]);
        asm volatile("cp.async.commit_group;" ::: "memory");
    };

    const unsigned asub = (warp_m >> 1) * 8192;
    unsigned abase_t[2];
#pragma unroll
    for (int mf = 0; mf < 2; ++mf) {
        int rowk = ((lane >> 4) & 1) * 8 + (lane & 7);
        int colb = (warp_m & 1) * 64 + mf * 32 + ((lane >> 3) & 1) * 16;
        abase_t[mf] = rowk * 128 + colb;
    }
    unsigned bbase[2];
#pragma unroll
    for (int nf2 = 0; nf2 < 2; ++nf2) {
        int rowB = warp_n * 32 + nf2 * 16 + ((lane >> 4) & 1) * 8 + (lane & 7);
        bbase[nf2] = rowB * 128 + ((lane >> 3) & 1) * 16;
    }

    float acc[2][4][4] = {};

    load_tile(0, 0);
    for (int t = 0; t < NKT; ++t) {
        if (t + 1 < NKT) {
            load_tile(t + 1, (t + 1) & 1);
            asm volatile("cp.async.wait_group 1;" ::: "memory");
        } else {
            asm volatile("cp.async.wait_group 0;" ::: "memory");
        }
        __syncthreads();

        const unsigned stA = sb + (t & 1) * STAGE;
        const unsigned stB = stA + OFF_B;
#pragma unroll
        for (int ks = 0; ks < 4; ++ks) {
            unsigned ah[2][4], bf[2][4];
#pragma unroll
            for (int mf = 0; mf < 2; ++mf)
                ldm_x4_t(ah[mf], stA + asub + swz(abase_t[mf] + ks * 2048));
#pragma unroll
            for (int nf2 = 0; nf2 < 2; ++nf2)
                ldm_x4(bf[nf2], stB + swz(bbase[nf2] + ks * 32));
#pragma unroll
            for (int mf = 0; mf < 2; ++mf)
#pragma unroll
                for (int nf = 0; nf < 4; ++nf)
                    mma16816(acc[mf][nf], ah[mf], &bf[nf >> 1][(nf & 1) * 2]);
        }
        __syncthreads();
    }

    const int rbase = m0 + warp_m * 32 + (lane >> 2);
    const int cbase0 = n0 + warp_n * 32 + (lane & 3) * 2;
#pragma unroll
    for (int mf = 0; mf < 2; ++mf)
#pragma unroll
        for (int nf = 0; nf < 4; ++nf) {
            const int cb = cbase0 + nf * 8;
#pragma unroll
            for (int h = 0; h < 2; ++h) {
                const int row = rbase + mf * 16 + h * 8;
                float2 v;
                v.x = acc[mf][nf][h * 2 + 0];
                v.y = acc[mf][nf][h * 2 + 1];
                *(float2*)(pout + (size_t)row * FDIM + cb) = v;
            }
        }
}

// ---------------------------------------------------------------------------
extern "C" void kernel_launch(void* const* d_in, const int* in_sizes, int n_in,
                              void* d_out, int out_size)
{
    const float* X     = (const float*)d_in[0];  // [N,F]
    const float* Lam   = (const float*)d_in[1];  // [N,N] diagonal
    const float* U     = (const float*)d_in[2];  // [N,N]
    const float* a     = (const float*)d_in[3];
    const float* b     = (const float*)d_in[4];
    const float* c     = (const float*)d_in[5];
    const float* alpha = (const float*)d_in[6];
    // d_in[7] = edge_index (unused by the reference math)
    const int nf = in_sizes[3];

    static bool attr_set = false;
    if (!attr_set) {
        cudaFuncSetAttribute(gemm1_k, cudaFuncAttributeMaxDynamicSharedMemorySize, SMEM_G);
        cudaFuncSetAttribute(gemm2_k, cudaFuncAttributeMaxDynamicSharedMemorySize, SMEM_G);
        attr_set = true;
    }

    prep_g_k<<<NDIM / 256, 256>>>(Lam, a, b, c, nf);
    dim3 bt(32, 8);
    prep_X_k<<<dim3(FDIM / 32, NDIM / 32), bt>>>(X);
    prep_U_k<<<dim3(NDIM / 32, NDIM / 32), bt>>>(U);

    // GEMM1: grid 2 x 32 x 4 = 256 CTAs
    gemm1_k<<<dim3(FDIM / BM, NDIM / BN, SPLITK), 256, SMEM_G>>>();
    merge1_k<<<(FDIM * NDIM / 4) / 256, 256>>>();
    // GEMM2: grid 16 x 4 x 4 = 256 CTAs
    gemm2_k<<<dim3(NDIM / BM, FDIM / BN, SPLITK), 256, SMEM_G>>>();
    merge2_k<<<(NDIM * FDIM / 4) / 256, 256>>>(X, alpha, (float*)d_out);
}